// round 14
// baseline (speedup 1.0000x reference)
#include <cuda_runtime.h>
#include <cuda_bf16.h>
#include <cuda_fp16.h>
#include <cstdint>
#include <math.h>

// ---------------- problem constants ----------------
#define NN     87381
#define HH     512
#define OUTF   256
#define NLEAF  65536
#define SLEAF  21845
static const int LS[10] = {0,1,5,21,85,341,1365,5461,21845,87381};

// converted weight offsets (elements), all [N,K=512] row-major fp16
// CX_l = [W_ioux_l (1536 rows) | W_fx_l (512 rows)]  (2048 x 512)
// CH_l = [W_iouh_l (1536 rows) | zeros  (512 rows)]  (2048 x 512)
#define OFF_WIN    0
#define OFF_CX0    262144
#define OFF_CX1    1310720
#define OFF_CH0    2359296
#define OFF_CH1    3407872
#define OFF_FH0    4456448
#define OFF_FH1    4718592
#define OFF_WOUT   4980736
#define WTOT       5111808
#define FXROW      786432     // 1536*512: offset of FX part within CX

// ---------------- scratch (device globals; no allocation) ----------
__device__ __half g_wh[WTOT];
__device__ __half g_x  [(size_t)NN * HH];
__device__ __half g_h0 [(size_t)NN * HH];
__device__ __half g_hi [(size_t)NN * HH];
__device__ __half g_hs [(size_t)16384 * HH];
__device__ float  g_cell[(size_t)NN * HH];
__device__ __half g_iou [(size_t)NLEAF * 1536];   // also holds [n,2048] internal
__device__ __half g_fh  [(size_t)NLEAF * HH];
__device__ float  g_part[(size_t)512 * HH];
__device__ float  g_cs  [HH];

// ---------------- portable PTX helpers (sm_80+ only) ----------------
__device__ __forceinline__ void mma_f16(float* c, const uint32_t* a, const uint32_t* b) {
    asm volatile(
        "mma.sync.aligned.m16n8k16.row.col.f32.f16.f16.f32 "
        "{%0,%1,%2,%3}, {%4,%5,%6,%7}, {%8,%9}, {%0,%1,%2,%3};"
        : "+f"(c[0]), "+f"(c[1]), "+f"(c[2]), "+f"(c[3])
        : "r"(a[0]), "r"(a[1]), "r"(a[2]), "r"(a[3]), "r"(b[0]), "r"(b[1]));
}
__device__ __forceinline__ void cp16z(uint16_t* dst, const void* src, bool pred) {
    uint32_t d = (uint32_t)__cvta_generic_to_shared(dst);
    int sz = pred ? 16 : 0;
    asm volatile("cp.async.cg.shared.global [%0], [%1], 16, %2;" :: "r"(d), "l"(src), "r"(sz));
}
__device__ __forceinline__ void cp_commit() { asm volatile("cp.async.commit_group;" ::: "memory"); }
__device__ __forceinline__ void cp_wait2()  { asm volatile("cp.async.wait_group 2;"  ::: "memory"); }

#define ASTR 24
#define TE   3072       // 128*24 elems (A tile / 128-row B tile)

// ---------------- big GEMM: CTA 128x128, warp 64x32 ----------------------
#define STGE 6144       // 2 tiles per stage (12288 B)

template <bool RELU, bool HOUT>
__global__ __launch_bounds__(256, 2) void gemm_mma(
    const __half* __restrict__ A1, const __half* __restrict__ B1,
    const __half* __restrict__ A2, const __half* __restrict__ B2,
    const float* __restrict__ bias,
    float* __restrict__ Cf, __half* __restrict__ Chf,
    int M, int Ntot)
{
    extern __shared__ uint16_t sm16[];
    const int t    = threadIdx.x;
    const int lane = t & 31, wid = t >> 5;
    const int q = lane >> 2, p = lane & 3;
    const int wm = wid >> 2, wn = wid & 3;       // 2 x 4 warps, tile 64x32
    const int bm = blockIdx.y * 128;
    const int bn = blockIdx.x * 128;

    const int r  = t >> 1;
    const int hf = t & 1;

    const int npass = (A2 != nullptr) ? 2 : 1;
    const int CT = npass * 32;

    float acc[4][4][4];
#pragma unroll
    for (int im = 0; im < 4; ++im)
#pragma unroll
        for (int in = 0; in < 4; ++in)
#pragma unroll
            for (int k = 0; k < 4; ++k) acc[im][in][k] = 0.f;

    auto stage = [&](int cc) {
        const int pass = cc >> 5, k0 = (cc & 31) * 16;
        const __half* A = pass ? A2 : A1;
        const __half* B = pass ? B2 : B1;
        uint16_t* stg = sm16 + (cc & 3) * STGE;
        const bool pa = (bm + r < M);
        const size_t asrc = (size_t)(bm + r) * 512 + k0 + hf * 8;
        const size_t bsrc = (size_t)(bn + r) * 512 + k0 + hf * 8;
        uint16_t* dst = stg + r * ASTR + hf * 8;
        cp16z(dst,      A + asrc, pa);
        cp16z(dst + TE, B + bsrc, true);
    };

    stage(0); cp_commit();
    if (CT > 1) { stage(1); cp_commit(); }

    for (int c = 0; c < CT; ++c) {
        if (c + 2 < CT) stage(c + 2);
        cp_commit();
        cp_wait2();
        __syncthreads();

        const uint16_t* stg = sm16 + (c & 3) * STGE;
        const uint16_t* AT = stg;
        const uint16_t* BT = stg + TE;

        uint32_t bh[4][2];
#pragma unroll
        for (int in = 0; in < 4; ++in) {
            int off = (wn * 32 + in * 8 + q) * ASTR + 2 * p;
            bh[in][0] = *(const uint32_t*)(BT + off);
            bh[in][1] = *(const uint32_t*)(BT + off + 8);
        }
#pragma unroll
        for (int im = 0; im < 4; ++im) {
            int off = (wm * 64 + im * 16 + q) * ASTR + 2 * p;
            uint32_t ah[4];
            ah[0] = *(const uint32_t*)(AT + off);
            ah[1] = *(const uint32_t*)(AT + off + 8 * ASTR);
            ah[2] = *(const uint32_t*)(AT + off + 8);
            ah[3] = *(const uint32_t*)(AT + off + 8 * ASTR + 8);
#pragma unroll
            for (int in = 0; in < 4; ++in) mma_f16(acc[im][in], ah, bh[in]);
        }
    }

#pragma unroll
    for (int im = 0; im < 4; ++im) {
#pragma unroll
        for (int in = 0; in < 4; ++in) {
            int row = bm + wm * 64 + im * 16 + q;
            int col = bn + wn * 32 + in * 8 + 2 * p;
            float b0 = 0.f, b1 = 0.f;
            if (bias) { b0 = bias[col]; b1 = bias[col + 1]; }
            float c0 = acc[im][in][0] + b0;
            float c1 = acc[im][in][1] + b1;
            float c2 = acc[im][in][2] + b0;
            float c3 = acc[im][in][3] + b1;
            if (RELU) {
                c0 = c0 > 0.f ? c0 : 0.f;  c1 = c1 > 0.f ? c1 : 0.f;
                c2 = c2 > 0.f ? c2 : 0.f;  c3 = c3 > 0.f ? c3 : 0.f;
            }
            if (HOUT) {
                if (row < M) {
                    __half2 hv = __floats2half2_rn(c0, c1);
                    *(uint32_t*)&Chf[(size_t)row * Ntot + col] = *(uint32_t*)&hv;
                }
                if (row + 8 < M) {
                    __half2 hv = __floats2half2_rn(c2, c3);
                    *(uint32_t*)&Chf[(size_t)(row + 8) * Ntot + col] = *(uint32_t*)&hv;
                }
            } else {
                if (row < M)
                    *(float2*)&Cf[(size_t)row * Ntot + col] = make_float2(c0, c1);
                if (row + 8 < M)
                    *(float2*)&Cf[(size_t)(row + 8) * Ntot + col] = make_float2(c2, c3);
            }
        }
    }
}

// ---------------- small-N GEMM: CTA 128x32, warp 64x8 --------------------
// For latency-bound small levels. fp16 output, no bias/relu.
#define STGE_S 3840     // A tile + 32-row B tile

__global__ __launch_bounds__(256, 4) void gemm_s(
    const __half* __restrict__ A1, const __half* __restrict__ B1,
    const __half* __restrict__ A2, const __half* __restrict__ B2,
    __half* __restrict__ Chf, int M, int Ntot)
{
    extern __shared__ uint16_t sm16[];
    const int t    = threadIdx.x;
    const int lane = t & 31, wid = t >> 5;
    const int q = lane >> 2, p = lane & 3;
    const int wm = wid >> 2, wn = wid & 3;       // warp tile 64x8
    const int bm = blockIdx.y * 128;
    const int bn = blockIdx.x * 32;

    const int r  = t >> 1;
    const int hf = t & 1;

    const int npass = (A2 != nullptr) ? 2 : 1;
    const int CT = npass * 32;

    float acc[4][4];
#pragma unroll
    for (int im = 0; im < 4; ++im)
#pragma unroll
        for (int k = 0; k < 4; ++k) acc[im][k] = 0.f;

    auto stage = [&](int cc) {
        const int pass = cc >> 5, k0 = (cc & 31) * 16;
        const __half* A = pass ? A2 : A1;
        const __half* B = pass ? B2 : B1;
        uint16_t* stg = sm16 + (cc & 3) * STGE_S;
        const bool pa = (bm + r < M);
        cp16z(stg + r * ASTR + hf * 8, A + (size_t)(bm + r) * 512 + k0 + hf * 8, pa);
        if (t < 64) {
            cp16z(stg + TE + r * ASTR + hf * 8,
                  B + (size_t)(bn + r) * 512 + k0 + hf * 8, true);
        }
    };

    stage(0); cp_commit();
    if (CT > 1) { stage(1); cp_commit(); }

    for (int c = 0; c < CT; ++c) {
        if (c + 2 < CT) stage(c + 2);
        cp_commit();
        cp_wait2();
        __syncthreads();

        const uint16_t* stg = sm16 + (c & 3) * STGE_S;
        const uint16_t* AT = stg;
        const uint16_t* BT = stg + TE;

        uint32_t bh[2];
        {
            int off = (wn * 8 + q) * ASTR + 2 * p;
            bh[0] = *(const uint32_t*)(BT + off);
            bh[1] = *(const uint32_t*)(BT + off + 8);
        }
#pragma unroll
        for (int im = 0; im < 4; ++im) {
            int off = (wm * 64 + im * 16 + q) * ASTR + 2 * p;
            uint32_t ah[4];
            ah[0] = *(const uint32_t*)(AT + off);
            ah[1] = *(const uint32_t*)(AT + off + 8 * ASTR);
            ah[2] = *(const uint32_t*)(AT + off + 8);
            ah[3] = *(const uint32_t*)(AT + off + 8 * ASTR + 8);
            mma_f16(acc[im], ah, bh);
        }
    }

#pragma unroll
    for (int im = 0; im < 4; ++im) {
        int row = bm + wm * 64 + im * 16 + q;
        int col = bn + wn * 8 + 2 * p;
        if (row < M) {
            __half2 hv = __floats2half2_rn(acc[im][0], acc[im][1]);
            *(uint32_t*)&Chf[(size_t)row * Ntot + col] = *(uint32_t*)&hv;
        }
        if (row + 8 < M) {
            __half2 hv = __floats2half2_rn(acc[im][2], acc[im][3]);
            *(uint32_t*)&Chf[(size_t)(row + 8) * Ntot + col] = *(uint32_t*)&hv;
        }
    }
}

// ---------------- conversions ---------------------------------------------
// One kernel for all weight transposes: W [512, Nc] fp32 -> [Nc, 512] fp16.
__global__ void conv_all(const float* __restrict__ W_in,
                         const float* __restrict__ W_ioux,
                         const float* __restrict__ W_iouh,
                         const float* __restrict__ W_fx,
                         const float* __restrict__ W_fh,
                         const float* __restrict__ W_out,
                         __half* __restrict__ wh)
{
    int idx = blockIdx.x * blockDim.x + threadIdx.x;
    const float* src; int Nc; __half* dst; int loc = idx;
    if      (loc < 262144)  { src = W_in;                Nc = 512;  dst = wh + OFF_WIN; }
    else if ((loc -= 262144) < 786432) { src = W_ioux;   Nc = 1536; dst = wh + OFF_CX0; }
    else if ((loc -= 786432) < 262144) { src = W_fx;     Nc = 512;  dst = wh + OFF_CX0 + FXROW; }
    else if ((loc -= 262144) < 786432) { src = W_ioux + 512 * 1536; Nc = 1536; dst = wh + OFF_CX1; }
    else if ((loc -= 786432) < 262144) { src = W_fx + 512 * 512;    Nc = 512;  dst = wh + OFF_CX1 + FXROW; }
    else if ((loc -= 262144) < 786432) { src = W_iouh;   Nc = 1536; dst = wh + OFF_CH0; }
    else if ((loc -= 786432) < 786432) { src = W_iouh + 512 * 1536; Nc = 1536; dst = wh + OFF_CH1; }
    else if ((loc -= 786432) < 262144) { src = W_fh;     Nc = 512;  dst = wh + OFF_FH0; }
    else if ((loc -= 262144) < 262144) { src = W_fh + 512 * 512;    Nc = 512;  dst = wh + OFF_FH1; }
    else if ((loc -= 262144) < 131072) { src = W_out;    Nc = 256;  dst = wh + OFF_WOUT; }
    else return;
    int n = loc >> 9, k = loc & 511;
    dst[loc] = __float2half(src[(size_t)k * Nc + n]);
}

__global__ void conv_x(const float* __restrict__ X, __half* __restrict__ Xh)
{
    size_t idx = (size_t)blockIdx.x * blockDim.x + threadIdx.x;
    if (idx >= (size_t)NN * HH) return;
    Xh[idx] = __float2half(X[idx]);
}

// ---------------- pointwise kernels (grouped: 4 rows/thread + hs) ---------
__device__ __forceinline__ float sigm(float x) { return 1.f / (1.f + expf(-x)); }
__device__ __forceinline__ float hf(const __half* p) { return __half2float(*p); }

__global__ void leaf_pw_g(const __half* __restrict__ iou,
                          const float* __restrict__ bix, const float* __restrict__ bih,
                          __half* __restrict__ H, float* __restrict__ cell,
                          __half* __restrict__ hs)
{
    int idx = blockIdx.x * blockDim.x + threadIdx.x;
    if (idx >= (NLEAF / 4) * HH) return;
    int rg = idx >> 9, j = idx & 511;
    float bi = bix[j]        + bih[j];
    float bo = bix[512 + j]  + bih[512 + j];
    float bu = bix[1024 + j] + bih[1024 + j];
    float hsv = 0.f;
#pragma unroll
    for (int k = 0; k < 4; ++k) {
        int r = 4 * rg + k;
        const __half* row = iou + (size_t)r * 1536;
        float i = sigm (hf(row + j)        + bi);
        float o = sigm (hf(row + 512 + j)  + bo);
        float u = tanhf(hf(row + 1024 + j) + bu);
        float c = i * u;
        size_t g = (size_t)(SLEAF + r) * HH + j;
        cell[g] = c;
        float hv = o * tanhf(c);
        H[g] = __float2half(hv);
        hsv += hv;
    }
    hs[(size_t)rg * HH + j] = __float2half(hsv);
}

// combined iou buffer row layout: [i|o|u|fx], stride 2048. n must be >= 4.
__global__ void int_pw_g(const __half* __restrict__ cio, const __half* __restrict__ fh,
                         const float* __restrict__ bix, const float* __restrict__ bih,
                         const float* __restrict__ bfx, const float* __restrict__ bfh,
                         __half* __restrict__ H, float* __restrict__ cell,
                         __half* __restrict__ hs,
                         int n, int s, int sc)
{
    int idx = blockIdx.x * blockDim.x + threadIdx.x;
    if (idx >= (n / 4) * HH) return;
    int rg = idx >> 9, j = idx & 511;
    float bi = bix[j]        + bih[j];
    float bo = bix[512 + j]  + bih[512 + j];
    float bu = bix[1024 + j] + bih[1024 + j];
    float bf = bfx[j] + bfh[j];
    float hsv = 0.f;
#pragma unroll
    for (int k = 0; k < 4; ++k) {
        int r = 4 * rg + k;
        const __half* row = cio + (size_t)r * 2048;
        float i = sigm (hf(row + j)        + bi);
        float o = sigm (hf(row + 512 + j)  + bo);
        float u = tanhf(hf(row + 1024 + j) + bu);
        float fxv = hf(row + 1536 + j) + bf;
        float acc = i * u;
#pragma unroll
        for (int kk = 0; kk < 4; ++kk) {
            float f = sigm(fxv + hf(fh + (size_t)(4 * r + kk) * HH + j));
            acc += f * cell[(size_t)(sc + 4 * r + kk) * HH + j];
        }
        size_t g = (size_t)(s + r) * HH + j;
        cell[g] = acc;
        float hv = o * tanhf(acc);
        H[g] = __float2half(hv);
        hsv += hv;
    }
    hs[(size_t)rg * HH + j] = __float2half(hsv);
}

// root level (n == 1): no hs output
__global__ void int_pw_root(const __half* __restrict__ cio, const __half* __restrict__ fh,
                            const float* __restrict__ bix, const float* __restrict__ bih,
                            const float* __restrict__ bfx, const float* __restrict__ bfh,
                            __half* __restrict__ H, float* __restrict__ cell)
{
    int j = blockIdx.x * blockDim.x + threadIdx.x;
    if (j >= HH) return;
    float i = sigm (hf(cio + j)        + bix[j]        + bih[j]);
    float o = sigm (hf(cio + 512 + j)  + bix[512 + j]  + bih[512 + j]);
    float u = tanhf(hf(cio + 1024 + j) + bix[1024 + j] + bih[1024 + j]);
    float fxv = hf(cio + 1536 + j) + bfx[j] + bfh[j];
    float acc = i * u;
#pragma unroll
    for (int kk = 0; kk < 4; ++kk) {
        float f = sigm(fxv + hf(fh + (size_t)kk * HH + j));
        acc += f * cell[(size_t)(1 + kk) * HH + j];
    }
    cell[j] = acc;
    H[j] = __float2half(o * tanhf(acc));
}

__global__ void colsum_part(const __half* __restrict__ H, float* __restrict__ part)
{
    int b = blockIdx.x;
    const int rows_per = (NN + 511) / 512;
    int r0 = b * rows_per;
    int r1 = r0 + rows_per; if (r1 > NN) r1 = NN;
    for (int j = threadIdx.x; j < HH; j += blockDim.x) {
        float s = 0.f;
        for (int r = r0; r < r1; ++r) s += __half2float(H[(size_t)r * HH + j]);
        part[(size_t)b * HH + j] = s;
    }
}

__global__ void colsum_final(const float* __restrict__ part, float* __restrict__ cs)
{
    int j = blockIdx.x * blockDim.x + threadIdx.x;
    if (j >= HH) return;
    float acc = 0.f;
    for (int b = 0; b < 512; ++b) acc += part[(size_t)b * HH + j];
    cs[j] = acc;
}

__global__ void tree_kernel(const float* __restrict__ cs, const float* __restrict__ W_out,
                            const float* __restrict__ b_out, float* __restrict__ out)
{
    int j = threadIdx.x;
    float acc = (float)NN * b_out[j];
    for (int k = 0; k < HH; ++k) acc += cs[k] * W_out[(size_t)k * OUTF + j];
    out[j] = acc;
}

// ---------------- driver ---------------------------------------------------
static void* symv(const void* s) { void* p = nullptr; cudaGetSymbolAddress(&p, s); return p; }

extern "C" void kernel_launch(void* const* d_in, const int* in_sizes, int n_in,
                              void* d_out, int out_size)
{
    (void)in_sizes; (void)n_in; (void)out_size;
    const float* x      = (const float*)d_in[0];
    const float* W_in   = (const float*)d_in[8];
    const float* b_in   = (const float*)d_in[9];
    const float* W_ioux = (const float*)d_in[10];
    const float* b_ioux = (const float*)d_in[11];
    const float* W_iouh = (const float*)d_in[12];
    const float* b_iouh = (const float*)d_in[13];
    const float* W_fx   = (const float*)d_in[14];
    const float* b_fx   = (const float*)d_in[15];
    const float* W_fh   = (const float*)d_in[16];
    const float* b_fh   = (const float*)d_in[17];
    const float* W_out  = (const float*)d_in[18];
    const float* b_out  = (const float*)d_in[19];
    float* out = (float*)d_out;

    __half* wh  = (__half*)symv(g_wh);
    __half* xh  = (__half*)symv(g_x);
    __half* h0  = (__half*)symv(g_h0);
    __half* hi  = (__half*)symv(g_hi);
    __half* hs  = (__half*)symv(g_hs);
    float*  cell = (float*)symv(g_cell);
    __half* iou  = (__half*)symv(g_iou);
    __half* fh   = (__half*)symv(g_fh);
    float*  part = (float*)symv(g_part);
    float*  cs   = (float*)symv(g_cs);

    const int SMB   = 4 * STGE * 2;     // 49152 B
    const int SMB_S = 4 * STGE_S * 2;   // 30720 B
    cudaFuncSetAttribute(gemm_mma<false,false>, cudaFuncAttributeMaxDynamicSharedMemorySize, SMB);
    cudaFuncSetAttribute(gemm_mma<false,true>,  cudaFuncAttributeMaxDynamicSharedMemorySize, SMB);
    cudaFuncSetAttribute(gemm_mma<true,true>,   cudaFuncAttributeMaxDynamicSharedMemorySize, SMB);

    // ---- conversions
    conv_all<<<(4587520 + 255) / 256, 256>>>(W_in, W_ioux, W_iouh, W_fx, W_fh, W_out, wh);
    cudaMemsetAsync(wh + OFF_CH0 + FXROW, 0, 512 * 512 * 2);
    cudaMemsetAsync(wh + OFF_CH1 + FXROW, 0, 512 * 512 * 2);
    conv_x<<<(int)(((size_t)NN * HH + 255) / 256), 256>>>(x, xh);

    const int MT_ALL = (NN + 127) / 128;   // 683

    // ---- input projection: h0 = relu(x @ W_in + b_in), fp16 out
    gemm_mma<true,true><<<dim3(4, MT_ALL), 256, SMB>>>(
        xh, wh + OFF_WIN, nullptr, nullptr,
        b_in, nullptr, h0, NN, HH);

    const int offCX[2] = {OFF_CX0, OFF_CX1};
    const int offCH[2] = {OFF_CH0, OFF_CH1};
    const int offFH[2] = {OFF_FH0, OFF_FH1};

    for (int l = 0; l < 2; ++l) {
        __half* hin  = (l == 0) ? h0 : hi;
        __half* hout = (l == 0) ? hi : h0;
        const float* Bix = b_ioux + (size_t)l * 1536;
        const float* Bih = b_iouh + (size_t)l * 1536;
        const float* Bfx = b_fx   + (size_t)l * HH;
        const float* Bfh = b_fh   + (size_t)l * HH;

        // leaf level: iou only (rows 0..1535 of CX = W_ioux), stride 1536, fp16 out
        gemm_mma<false,true><<<dim3(12, NLEAF / 128), 256, SMB>>>(
            hin + (size_t)SLEAF * HH, wh + offCX[l],
            nullptr, nullptr,
            nullptr, nullptr, iou, NLEAF, 1536);
        leaf_pw_g<<<((NLEAF / 4) * HH) / 256, 256>>>(iou, Bix, Bih, hout, cell, hs);

        for (int d = 7; d >= 0; --d) {
            int s  = LS[d];
            int n  = LS[d + 1] - LS[d];
            int sc = LS[d + 1];
            int mt  = (n + 127) / 128;
            int mt4 = (4 * n + 127) / 128;

            // dual GEMM: C[n,2048] = hin@[Wix|Wfx] + hs@[Wih|0], fp16 out
            if (n >= 4096) {
                gemm_mma<false,true><<<dim3(16, mt), 256, SMB>>>(
                    hin + (size_t)s * HH, wh + offCX[l],
                    hs, wh + offCH[l],
                    nullptr, nullptr, iou, n, 2048);
            } else {
                gemm_s<<<dim3(64, mt), 256, SMB_S>>>(
                    hin + (size_t)s * HH, wh + offCX[l],
                    hs, wh + offCH[l], iou, n, 2048);
            }
            // fh GEMM: [4n,512] = children_H @ W_fh, fp16 out
            if (n >= 1024) {
                gemm_mma<false,true><<<dim3(4, mt4), 256, SMB>>>(
                    hout + (size_t)sc * HH, wh + offFH[l],
                    nullptr, nullptr,
                    nullptr, nullptr, fh, 4 * n, HH);
            } else {
                gemm_s<<<dim3(16, mt4), 256, SMB_S>>>(
                    hout + (size_t)sc * HH, wh + offFH[l],
                    nullptr, nullptr, fh, 4 * n, HH);
            }
            if (d > 0) {
                int nblk = ((n / 4) * HH + 255) / 256;
                int_pw_g<<<nblk, 256>>>(iou, fh, Bix, Bih, Bfx, Bfh,
                                        hout, cell, hs, n, s, sc);
            } else {
                int_pw_root<<<2, 256>>>(iou, fh, Bix, Bih, Bfx, Bfh, hout, cell);
            }
        }
    }

    // node_emb = h0 @ W_out + b_out (fp32 out to harness buffer)
    gemm_mma<false,false><<<dim3(2, MT_ALL), 256, SMB>>>(
        h0, wh + OFF_WOUT, nullptr, nullptr,
        b_out, out, nullptr, NN, OUTF);

    // tree_emb
    colsum_part<<<512, 256>>>(h0, part);
    colsum_final<<<2, 256>>>(part, cs);
    tree_kernel<<<1, 256>>>(cs, W_out, b_out, out + (size_t)NN * OUTF);
}

// round 15
// speedup vs baseline: 1.1455x; 1.1455x over previous
#include <cuda_runtime.h>
#include <cuda_bf16.h>
#include <cuda_fp16.h>
#include <cstdint>
#include <math.h>

// ---------------- problem constants ----------------
#define NN     87381
#define HH     512
#define OUTF   256
#define NLEAF  65536
#define SLEAF  21845
static const int LS[10] = {0,1,5,21,85,341,1365,5461,21845,87381};

// converted weight offsets (elements), all [N,K=512] row-major fp16
// CX_l = [W_ioux_l (1536 rows) | W_fx_l (512 rows)]  (2048 x 512)
// CH_l = [W_iouh_l (1536 rows) | zeros  (512 rows)]  (2048 x 512)
#define OFF_WIN    0
#define OFF_CX0    262144
#define OFF_CX1    1310720
#define OFF_CH0    2359296
#define OFF_CH1    3407872
#define OFF_FH0    4456448
#define OFF_FH1    4718592
#define OFF_WOUT   4980736
#define WTOT       5111808
#define FXROW      786432     // 1536*512: offset of FX part within CX

// ---------------- scratch (device globals; no allocation) ----------
__device__ __half g_wh[WTOT];
__device__ __half g_x  [(size_t)NN * HH];
__device__ __half g_h0 [(size_t)NN * HH];
__device__ __half g_hi [(size_t)NN * HH];
__device__ __half g_hs [(size_t)16384 * HH];
__device__ float  g_cell[(size_t)NN * HH];
__device__ __half g_iou [(size_t)NLEAF * 1536];   // also holds [n,2048] internal
__device__ __half g_fh  [(size_t)NLEAF * HH];
__device__ float  g_part[(size_t)512 * HH];
__device__ float  g_cs  [HH];

// ---------------- portable PTX helpers (sm_80+ only) ----------------
__device__ __forceinline__ void mma_f16(float* c, const uint32_t* a, const uint32_t* b) {
    asm volatile(
        "mma.sync.aligned.m16n8k16.row.col.f32.f16.f16.f32 "
        "{%0,%1,%2,%3}, {%4,%5,%6,%7}, {%8,%9}, {%0,%1,%2,%3};"
        : "+f"(c[0]), "+f"(c[1]), "+f"(c[2]), "+f"(c[3])
        : "r"(a[0]), "r"(a[1]), "r"(a[2]), "r"(a[3]), "r"(b[0]), "r"(b[1]));
}
__device__ __forceinline__ void cp16z(uint16_t* dst, const void* src, bool pred) {
    uint32_t d = (uint32_t)__cvta_generic_to_shared(dst);
    int sz = pred ? 16 : 0;
    asm volatile("cp.async.cg.shared.global [%0], [%1], 16, %2;" :: "r"(d), "l"(src), "r"(sz));
}
__device__ __forceinline__ void cp_commit() { asm volatile("cp.async.commit_group;" ::: "memory"); }
__device__ __forceinline__ void cp_wait2()  { asm volatile("cp.async.wait_group 2;"  ::: "memory"); }

// K-chunk 32 staging: row stride 40 elems (32 + 8 pad) -> conflict-free
#define ASTR 40
#define TE   5120       // 128*40 elems (A tile / 128-row B tile)

// ---------------- big GEMM: CTA 128x128, warp 64x32, K chunk 32 ----------
#define STGE 10240      // A + B tile per stage (20480 B)

template <bool RELU, bool HOUT>
__global__ __launch_bounds__(256, 2) void gemm_mma(
    const __half* __restrict__ A1, const __half* __restrict__ B1,
    const __half* __restrict__ A2, const __half* __restrict__ B2,
    const float* __restrict__ bias,
    float* __restrict__ Cf, __half* __restrict__ Chf,
    int M, int Ntot)
{
    extern __shared__ uint16_t sm16[];
    const int t    = threadIdx.x;
    const int lane = t & 31, wid = t >> 5;
    const int q = lane >> 2, p = lane & 3;
    const int wm = wid >> 2, wn = wid & 3;       // 2 x 4 warps, tile 64x32
    const int bm = blockIdx.y * 128;
    const int bn = blockIdx.x * 128;

    const int npass = (A2 != nullptr) ? 2 : 1;
    const int CT = npass * 16;                   // K=512 per pass, chunk 32

    float acc[4][4][4];
#pragma unroll
    for (int im = 0; im < 4; ++im)
#pragma unroll
        for (int in = 0; in < 4; ++in)
#pragma unroll
            for (int k = 0; k < 4; ++k) acc[im][in][k] = 0.f;

    auto stage = [&](int cc) {
        const int pass = cc >> 4, k0 = (cc & 15) * 32;
        const __half* A = pass ? A2 : A1;
        const __half* B = pass ? B2 : B1;
        uint16_t* stg = sm16 + (cc & 3) * STGE;
#pragma unroll
        for (int i = t; i < 512; i += 256) {     // 128 rows x 4 segs of 8
            int row = i >> 2, seg = i & 3;
            const bool pa = (bm + row < M);
            cp16z(stg + row * ASTR + seg * 8,
                  A + (size_t)(bm + row) * 512 + k0 + seg * 8, pa);
            cp16z(stg + TE + row * ASTR + seg * 8,
                  B + (size_t)(bn + row) * 512 + k0 + seg * 8, true);
        }
    };

    stage(0); cp_commit();
    if (CT > 1) { stage(1); cp_commit(); }

    for (int c = 0; c < CT; ++c) {
        if (c + 2 < CT) stage(c + 2);
        cp_commit();
        cp_wait2();
        __syncthreads();

        const uint16_t* stg = sm16 + (c & 3) * STGE;
        const uint16_t* AT = stg;
        const uint16_t* BT = stg + TE;

#pragma unroll
        for (int k2 = 0; k2 < 2; ++k2) {
            const int ko = k2 * 16;
            uint32_t bh[4][2];
#pragma unroll
            for (int in = 0; in < 4; ++in) {
                int off = (wn * 32 + in * 8 + q) * ASTR + ko + 2 * p;
                bh[in][0] = *(const uint32_t*)(BT + off);
                bh[in][1] = *(const uint32_t*)(BT + off + 8);
            }
#pragma unroll
            for (int im = 0; im < 4; ++im) {
                int off = (wm * 64 + im * 16 + q) * ASTR + ko + 2 * p;
                uint32_t ah[4];
                ah[0] = *(const uint32_t*)(AT + off);
                ah[1] = *(const uint32_t*)(AT + off + 8 * ASTR);
                ah[2] = *(const uint32_t*)(AT + off + 8);
                ah[3] = *(const uint32_t*)(AT + off + 8 * ASTR + 8);
#pragma unroll
                for (int in = 0; in < 4; ++in) mma_f16(acc[im][in], ah, bh[in]);
            }
        }
    }

#pragma unroll
    for (int im = 0; im < 4; ++im) {
#pragma unroll
        for (int in = 0; in < 4; ++in) {
            int row = bm + wm * 64 + im * 16 + q;
            int col = bn + wn * 32 + in * 8 + 2 * p;
            float b0 = 0.f, b1 = 0.f;
            if (bias) { b0 = bias[col]; b1 = bias[col + 1]; }
            float c0 = acc[im][in][0] + b0;
            float c1 = acc[im][in][1] + b1;
            float c2 = acc[im][in][2] + b0;
            float c3 = acc[im][in][3] + b1;
            if (RELU) {
                c0 = c0 > 0.f ? c0 : 0.f;  c1 = c1 > 0.f ? c1 : 0.f;
                c2 = c2 > 0.f ? c2 : 0.f;  c3 = c3 > 0.f ? c3 : 0.f;
            }
            if (HOUT) {
                if (row < M) {
                    __half2 hv = __floats2half2_rn(c0, c1);
                    *(uint32_t*)&Chf[(size_t)row * Ntot + col] = *(uint32_t*)&hv;
                }
                if (row + 8 < M) {
                    __half2 hv = __floats2half2_rn(c2, c3);
                    *(uint32_t*)&Chf[(size_t)(row + 8) * Ntot + col] = *(uint32_t*)&hv;
                }
            } else {
                if (row < M)
                    *(float2*)&Cf[(size_t)row * Ntot + col] = make_float2(c0, c1);
                if (row + 8 < M)
                    *(float2*)&Cf[(size_t)(row + 8) * Ntot + col] = make_float2(c2, c3);
            }
        }
    }
}

// ---------------- small-N GEMM: CTA 128x32, warp 64x8, K chunk 32 --------
#define STGE_S 6400     // A tile (5120) + 32-row B tile (1280), 12800 B

__global__ __launch_bounds__(256, 4) void gemm_s(
    const __half* __restrict__ A1, const __half* __restrict__ B1,
    const __half* __restrict__ A2, const __half* __restrict__ B2,
    __half* __restrict__ Chf, int M, int Ntot)
{
    extern __shared__ uint16_t sm16[];
    const int t    = threadIdx.x;
    const int lane = t & 31, wid = t >> 5;
    const int q = lane >> 2, p = lane & 3;
    const int wm = wid >> 2, wn = wid & 3;       // warp tile 64x8
    const int bm = blockIdx.y * 128;
    const int bn = blockIdx.x * 32;

    const int npass = (A2 != nullptr) ? 2 : 1;
    const int CT = npass * 16;

    float acc[4][4];
#pragma unroll
    for (int im = 0; im < 4; ++im)
#pragma unroll
        for (int k = 0; k < 4; ++k) acc[im][k] = 0.f;

    auto stage = [&](int cc) {
        const int pass = cc >> 4, k0 = (cc & 15) * 32;
        const __half* A = pass ? A2 : A1;
        const __half* B = pass ? B2 : B1;
        uint16_t* stg = sm16 + (cc & 3) * STGE_S;
#pragma unroll
        for (int i = t; i < 512; i += 256) {
            int row = i >> 2, seg = i & 3;
            const bool pa = (bm + row < M);
            cp16z(stg + row * ASTR + seg * 8,
                  A + (size_t)(bm + row) * 512 + k0 + seg * 8, pa);
        }
        if (t < 128) {
            int row = t >> 2, seg = t & 3;
            cp16z(stg + TE + row * ASTR + seg * 8,
                  B + (size_t)(bn + row) * 512 + k0 + seg * 8, true);
        }
    };

    stage(0); cp_commit();
    if (CT > 1) { stage(1); cp_commit(); }

    for (int c = 0; c < CT; ++c) {
        if (c + 2 < CT) stage(c + 2);
        cp_commit();
        cp_wait2();
        __syncthreads();

        const uint16_t* stg = sm16 + (c & 3) * STGE_S;
        const uint16_t* AT = stg;
        const uint16_t* BT = stg + TE;

#pragma unroll
        for (int k2 = 0; k2 < 2; ++k2) {
            const int ko = k2 * 16;
            uint32_t bh[2];
            {
                int off = (wn * 8 + q) * ASTR + ko + 2 * p;
                bh[0] = *(const uint32_t*)(BT + off);
                bh[1] = *(const uint32_t*)(BT + off + 8);
            }
#pragma unroll
            for (int im = 0; im < 4; ++im) {
                int off = (wm * 64 + im * 16 + q) * ASTR + ko + 2 * p;
                uint32_t ah[4];
                ah[0] = *(const uint32_t*)(AT + off);
                ah[1] = *(const uint32_t*)(AT + off + 8 * ASTR);
                ah[2] = *(const uint32_t*)(AT + off + 8);
                ah[3] = *(const uint32_t*)(AT + off + 8 * ASTR + 8);
                mma_f16(acc[im], ah, bh);
            }
        }
    }

#pragma unroll
    for (int im = 0; im < 4; ++im) {
        int row = bm + wm * 64 + im * 16 + q;
        int col = bn + wn * 8 + 2 * p;
        if (row < M) {
            __half2 hv = __floats2half2_rn(acc[im][0], acc[im][1]);
            *(uint32_t*)&Chf[(size_t)row * Ntot + col] = *(uint32_t*)&hv;
        }
        if (row + 8 < M) {
            __half2 hv = __floats2half2_rn(acc[im][2], acc[im][3]);
            *(uint32_t*)&Chf[(size_t)(row + 8) * Ntot + col] = *(uint32_t*)&hv;
        }
    }
}

// ---------------- conversions ---------------------------------------------
__global__ void conv_all(const float* __restrict__ W_in,
                         const float* __restrict__ W_ioux,
                         const float* __restrict__ W_iouh,
                         const float* __restrict__ W_fx,
                         const float* __restrict__ W_fh,
                         const float* __restrict__ W_out,
                         __half* __restrict__ wh)
{
    int idx = blockIdx.x * blockDim.x + threadIdx.x;
    const float* src; int Nc; __half* dst; int loc = idx;
    if      (loc < 262144)  { src = W_in;                Nc = 512;  dst = wh + OFF_WIN; }
    else if ((loc -= 262144) < 786432) { src = W_ioux;   Nc = 1536; dst = wh + OFF_CX0; }
    else if ((loc -= 786432) < 262144) { src = W_fx;     Nc = 512;  dst = wh + OFF_CX0 + FXROW; }
    else if ((loc -= 262144) < 786432) { src = W_ioux + 512 * 1536; Nc = 1536; dst = wh + OFF_CX1; }
    else if ((loc -= 786432) < 262144) { src = W_fx + 512 * 512;    Nc = 512;  dst = wh + OFF_CX1 + FXROW; }
    else if ((loc -= 262144) < 786432) { src = W_iouh;   Nc = 1536; dst = wh + OFF_CH0; }
    else if ((loc -= 786432) < 786432) { src = W_iouh + 512 * 1536; Nc = 1536; dst = wh + OFF_CH1; }
    else if ((loc -= 786432) < 262144) { src = W_fh;     Nc = 512;  dst = wh + OFF_FH0; }
    else if ((loc -= 262144) < 262144) { src = W_fh + 512 * 512;    Nc = 512;  dst = wh + OFF_FH1; }
    else if ((loc -= 262144) < 131072) { src = W_out;    Nc = 256;  dst = wh + OFF_WOUT; }
    else return;
    int n = loc >> 9, k = loc & 511;
    dst[loc] = __float2half(src[(size_t)k * Nc + n]);
}

__global__ void conv_x(const float* __restrict__ X, __half* __restrict__ Xh)
{
    size_t idx = (size_t)blockIdx.x * blockDim.x + threadIdx.x;
    if (idx >= (size_t)NN * HH) return;
    Xh[idx] = __float2half(X[idx]);
}

// ---------------- pointwise kernels (grouped: 4 rows/thread + hs) ---------
__device__ __forceinline__ float sigm(float x) { return 1.f / (1.f + expf(-x)); }
__device__ __forceinline__ float hf(const __half* p) { return __half2float(*p); }

__global__ void leaf_pw_g(const __half* __restrict__ iou,
                          const float* __restrict__ bix, const float* __restrict__ bih,
                          __half* __restrict__ H, float* __restrict__ cell,
                          __half* __restrict__ hs)
{
    int idx = blockIdx.x * blockDim.x + threadIdx.x;
    if (idx >= (NLEAF / 4) * HH) return;
    int rg = idx >> 9, j = idx & 511;
    float bi = bix[j]        + bih[j];
    float bo = bix[512 + j]  + bih[512 + j];
    float bu = bix[1024 + j] + bih[1024 + j];
    float hsv = 0.f;
#pragma unroll
    for (int k = 0; k < 4; ++k) {
        int r = 4 * rg + k;
        const __half* row = iou + (size_t)r * 1536;
        float i = sigm (hf(row + j)        + bi);
        float o = sigm (hf(row + 512 + j)  + bo);
        float u = tanhf(hf(row + 1024 + j) + bu);
        float c = i * u;
        size_t g = (size_t)(SLEAF + r) * HH + j;
        cell[g] = c;
        float hv = o * tanhf(c);
        H[g] = __float2half(hv);
        hsv += hv;
    }
    hs[(size_t)rg * HH + j] = __float2half(hsv);
}

// combined iou buffer row layout: [i|o|u|fx], stride 2048. n must be >= 4.
__global__ void int_pw_g(const __half* __restrict__ cio, const __half* __restrict__ fh,
                         const float* __restrict__ bix, const float* __restrict__ bih,
                         const float* __restrict__ bfx, const float* __restrict__ bfh,
                         __half* __restrict__ H, float* __restrict__ cell,
                         __half* __restrict__ hs,
                         int n, int s, int sc)
{
    int idx = blockIdx.x * blockDim.x + threadIdx.x;
    if (idx >= (n / 4) * HH) return;
    int rg = idx >> 9, j = idx & 511;
    float bi = bix[j]        + bih[j];
    float bo = bix[512 + j]  + bih[512 + j];
    float bu = bix[1024 + j] + bih[1024 + j];
    float bf = bfx[j] + bfh[j];
    float hsv = 0.f;
#pragma unroll
    for (int k = 0; k < 4; ++k) {
        int r = 4 * rg + k;
        const __half* row = cio + (size_t)r * 2048;
        float i = sigm (hf(row + j)        + bi);
        float o = sigm (hf(row + 512 + j)  + bo);
        float u = tanhf(hf(row + 1024 + j) + bu);
        float fxv = hf(row + 1536 + j) + bf;
        float acc = i * u;
#pragma unroll
        for (int kk = 0; kk < 4; ++kk) {
            float f = sigm(fxv + hf(fh + (size_t)(4 * r + kk) * HH + j));
            acc += f * cell[(size_t)(sc + 4 * r + kk) * HH + j];
        }
        size_t g = (size_t)(s + r) * HH + j;
        cell[g] = acc;
        float hv = o * tanhf(acc);
        H[g] = __float2half(hv);
        hsv += hv;
    }
    hs[(size_t)rg * HH + j] = __float2half(hsv);
}

// root level (n == 1): no hs output
__global__ void int_pw_root(const __half* __restrict__ cio, const __half* __restrict__ fh,
                            const float* __restrict__ bix, const float* __restrict__ bih,
                            const float* __restrict__ bfx, const float* __restrict__ bfh,
                            __half* __restrict__ H, float* __restrict__ cell)
{
    int j = blockIdx.x * blockDim.x + threadIdx.x;
    if (j >= HH) return;
    float i = sigm (hf(cio + j)        + bix[j]        + bih[j]);
    float o = sigm (hf(cio + 512 + j)  + bix[512 + j]  + bih[512 + j]);
    float u = tanhf(hf(cio + 1024 + j) + bix[1024 + j] + bih[1024 + j]);
    float fxv = hf(cio + 1536 + j) + bfx[j] + bfh[j];
    float acc = i * u;
#pragma unroll
    for (int kk = 0; kk < 4; ++kk) {
        float f = sigm(fxv + hf(fh + (size_t)kk * HH + j));
        acc += f * cell[(size_t)(1 + kk) * HH + j];
    }
    cell[j] = acc;
    H[j] = __float2half(o * tanhf(acc));
}

__global__ void colsum_part(const __half* __restrict__ H, float* __restrict__ part)
{
    int b = blockIdx.x;
    const int rows_per = (NN + 511) / 512;
    int r0 = b * rows_per;
    int r1 = r0 + rows_per; if (r1 > NN) r1 = NN;
    for (int j = threadIdx.x; j < HH; j += blockDim.x) {
        float s = 0.f;
        for (int r = r0; r < r1; ++r) s += __half2float(H[(size_t)r * HH + j]);
        part[(size_t)b * HH + j] = s;
    }
}

__global__ void colsum_final(const float* __restrict__ part, float* __restrict__ cs)
{
    int j = blockIdx.x * blockDim.x + threadIdx.x;
    if (j >= HH) return;
    float acc = 0.f;
    for (int b = 0; b < 512; ++b) acc += part[(size_t)b * HH + j];
    cs[j] = acc;
}

__global__ void tree_kernel(const float* __restrict__ cs, const float* __restrict__ W_out,
                            const float* __restrict__ b_out, float* __restrict__ out)
{
    int j = threadIdx.x;
    float acc = (float)NN * b_out[j];
    for (int k = 0; k < HH; ++k) acc += cs[k] * W_out[(size_t)k * OUTF + j];
    out[j] = acc;
}

// ---------------- driver ---------------------------------------------------
static void* symv(const void* s) { void* p = nullptr; cudaGetSymbolAddress(&p, s); return p; }

extern "C" void kernel_launch(void* const* d_in, const int* in_sizes, int n_in,
                              void* d_out, int out_size)
{
    (void)in_sizes; (void)n_in; (void)out_size;
    const float* x      = (const float*)d_in[0];
    const float* W_in   = (const float*)d_in[8];
    const float* b_in   = (const float*)d_in[9];
    const float* W_ioux = (const float*)d_in[10];
    const float* b_ioux = (const float*)d_in[11];
    const float* W_iouh = (const float*)d_in[12];
    const float* b_iouh = (const float*)d_in[13];
    const float* W_fx   = (const float*)d_in[14];
    const float* b_fx   = (const float*)d_in[15];
    const float* W_fh   = (const float*)d_in[16];
    const float* b_fh   = (const float*)d_in[17];
    const float* W_out  = (const float*)d_in[18];
    const float* b_out  = (const float*)d_in[19];
    float* out = (float*)d_out;

    __half* wh  = (__half*)symv(g_wh);
    __half* xh  = (__half*)symv(g_x);
    __half* h0  = (__half*)symv(g_h0);
    __half* hi  = (__half*)symv(g_hi);
    __half* hs  = (__half*)symv(g_hs);
    float*  cell = (float*)symv(g_cell);
    __half* iou  = (__half*)symv(g_iou);
    __half* fh   = (__half*)symv(g_fh);
    float*  part = (float*)symv(g_part);
    float*  cs   = (float*)symv(g_cs);

    const int SMB   = 4 * STGE * 2;     // 81920 B
    const int SMB_S = 4 * STGE_S * 2;   // 51200 B
    cudaFuncSetAttribute(gemm_mma<false,false>, cudaFuncAttributeMaxDynamicSharedMemorySize, SMB);
    cudaFuncSetAttribute(gemm_mma<false,true>,  cudaFuncAttributeMaxDynamicSharedMemorySize, SMB);
    cudaFuncSetAttribute(gemm_mma<true,true>,   cudaFuncAttributeMaxDynamicSharedMemorySize, SMB);
    cudaFuncSetAttribute(gemm_s,                cudaFuncAttributeMaxDynamicSharedMemorySize, SMB_S);

    // ---- conversions
    conv_all<<<(4587520 + 255) / 256, 256>>>(W_in, W_ioux, W_iouh, W_fx, W_fh, W_out, wh);
    cudaMemsetAsync(wh + OFF_CH0 + FXROW, 0, 512 * 512 * 2);
    cudaMemsetAsync(wh + OFF_CH1 + FXROW, 0, 512 * 512 * 2);
    conv_x<<<(int)(((size_t)NN * HH + 255) / 256), 256>>>(x, xh);

    const int MT_ALL = (NN + 127) / 128;   // 683

    // ---- input projection: h0 = relu(x @ W_in + b_in), fp16 out
    gemm_mma<true,true><<<dim3(4, MT_ALL), 256, SMB>>>(
        xh, wh + OFF_WIN, nullptr, nullptr,
        b_in, nullptr, h0, NN, HH);

    const int offCX[2] = {OFF_CX0, OFF_CX1};
    const int offCH[2] = {OFF_CH0, OFF_CH1};
    const int offFH[2] = {OFF_FH0, OFF_FH1};

    for (int l = 0; l < 2; ++l) {
        __half* hin  = (l == 0) ? h0 : hi;
        __half* hout = (l == 0) ? hi : h0;
        const float* Bix = b_ioux + (size_t)l * 1536;
        const float* Bih = b_iouh + (size_t)l * 1536;
        const float* Bfx = b_fx   + (size_t)l * HH;
        const float* Bfh = b_fh   + (size_t)l * HH;

        // leaf level: iou only (rows 0..1535 of CX = W_ioux), stride 1536, fp16 out
        gemm_mma<false,true><<<dim3(12, NLEAF / 128), 256, SMB>>>(
            hin + (size_t)SLEAF * HH, wh + offCX[l],
            nullptr, nullptr,
            nullptr, nullptr, iou, NLEAF, 1536);
        leaf_pw_g<<<((NLEAF / 4) * HH) / 256, 256>>>(iou, Bix, Bih, hout, cell, hs);

        for (int d = 7; d >= 0; --d) {
            int s  = LS[d];
            int n  = LS[d + 1] - LS[d];
            int sc = LS[d + 1];
            int mt  = (n + 127) / 128;
            int mt4 = (4 * n + 127) / 128;

            // dual GEMM: C[n,2048] = hin@[Wix|Wfx] + hs@[Wih|0], fp16 out
            if (n >= 4096) {
                gemm_mma<false,true><<<dim3(16, mt), 256, SMB>>>(
                    hin + (size_t)s * HH, wh + offCX[l],
                    hs, wh + offCH[l],
                    nullptr, nullptr, iou, n, 2048);
            } else {
                gemm_s<<<dim3(64, mt), 256, SMB_S>>>(
                    hin + (size_t)s * HH, wh + offCX[l],
                    hs, wh + offCH[l], iou, n, 2048);
            }
            // fh GEMM: [4n,512] = children_H @ W_fh, fp16 out
            if (n >= 1024) {
                gemm_mma<false,true><<<dim3(4, mt4), 256, SMB>>>(
                    hout + (size_t)sc * HH, wh + offFH[l],
                    nullptr, nullptr,
                    nullptr, nullptr, fh, 4 * n, HH);
            } else {
                gemm_s<<<dim3(16, mt4), 256, SMB_S>>>(
                    hout + (size_t)sc * HH, wh + offFH[l],
                    nullptr, nullptr, fh, 4 * n, HH);
            }
            if (d > 0) {
                int nblk = ((n / 4) * HH + 255) / 256;
                int_pw_g<<<nblk, 256>>>(iou, fh, Bix, Bih, Bfx, Bfh,
                                        hout, cell, hs, n, s, sc);
            } else {
                int_pw_root<<<2, 256>>>(iou, fh, Bix, Bih, Bfx, Bfh, hout, cell);
            }
        }
    }

    // node_emb = h0 @ W_out + b_out (fp32 out to harness buffer)
    gemm_mma<false,false><<<dim3(2, MT_ALL), 256, SMB>>>(
        h0, wh + OFF_WOUT, nullptr, nullptr,
        b_out, out, nullptr, NN, OUTF);

    // tree_emb
    colsum_part<<<512, 256>>>(h0, part);
    colsum_final<<<2, 256>>>(part, cs);
    tree_kernel<<<1, 256>>>(cs, W_out, b_out, out + (size_t)NN * OUTF);
}